// round 16
// baseline (speedup 1.0000x reference)
#include <cuda_runtime.h>
#include <cuda_fp16.h>
#include <cstdint>

#define NN 100000
#define EE 1600000
#define FULL 0xffffffffu
#define NB_SCAN 196

// ---------------- scratch (static device globals; no allocation) ----------------
// NOTE: g_cnt/g_state are zero at module load and re-zeroed by k_fill each call
// (after k_scan consumes them), so k_prep's histogram always starts from zero.
__device__ __align__(16) int   g_cnt[NN];
__device__ __align__(16) int   g_row_start[NN + 1];
__device__ __align__(16) int   g_cursor[NN];
__device__ __align__(16) int   g_csr[EE];
__device__ __align__(16) unsigned int g_state[256];   // lookback: flag(2b)|value(30b)
__device__ __align__(16) __half g_x16[12800000];      // x in fp16 [N][128]
__device__ __align__(16) __half g_aggx16[12800000];   // mean-agg in fp16 [N][128]
__device__ __align__(16) float g_u[NN * 4];
__device__ __align__(16) float g_v[NN * 4];
__device__ __align__(16) __half g_w1h[65536];         // [256 out][256 k] fp16

// ---------------- prep: W->fp16, x->fp16, degree histogram ----------------
__global__ void k_prep(const float* __restrict__ w1l, const float* __restrict__ w1r,
                       const float* __restrict__ x, const int* __restrict__ ei) {
    int idx = blockIdx.x * 256 + threadIdx.x;   // 131072 threads
    // weights (first 65536 threads)
    if (idx < 65536) {
        int out = idx >> 8, k = idx & 255;
        float v = (k < 128) ? w1l[out * 128 + k] : w1r[out * 128 + (k - 128)];
        g_w1h[idx] = __float2half_rn(v);
    }
    // x -> fp16 (1.6M uint4 = 12.8M halves)
    const float4* xf = (const float4*)x;
    for (int i = idx; i < 1600000; i += 131072) {
        float4 a = xf[2 * i], b = xf[2 * i + 1];
        union { __half2 h2[4]; uint4 u; } P;
        P.h2[0] = __floats2half2_rn(a.x, a.y);
        P.h2[1] = __floats2half2_rn(a.z, a.w);
        P.h2[2] = __floats2half2_rn(b.x, b.y);
        P.h2[3] = __floats2half2_rn(b.z, b.w);
        ((uint4*)g_x16)[i] = P.u;
    }
    // in-degree histogram (g_cnt pre-zeroed by previous call's k_fill / module load)
    for (int e = idx; e < EE; e += 131072)
        atomicAdd(&g_cnt[ei[EE + e]], 1);
}

// ---------------- single-kernel exclusive scan (decoupled lookback) ----------------
__global__ __launch_bounds__(512) void k_scan() {
    int b = blockIdx.x, t = threadIdx.x;
    int gid = b * 512 + t;
    int v = (gid < NN) ? g_cnt[gid] : 0;

    __shared__ int s[512];
    s[t] = v;
    for (int off = 1; off < 512; off <<= 1) {
        __syncthreads();
        int add = (t >= off) ? s[t - off] : 0;
        __syncthreads();
        s[t] += add;
    }
    __syncthreads();
    int incl  = s[t];
    int total = s[511];

    __shared__ int sExcl;
    if (t == 0) {
        if (b == 0) {
            atomicExch(&g_state[0], (2u << 30) | (unsigned)total);
            sExcl = 0;
        } else {
            atomicExch(&g_state[b], (1u << 30) | (unsigned)total);
            int excl = 0, j = b - 1;
            while (true) {
                unsigned st;
                do { st = atomicAdd(&g_state[j], 0u); } while ((st >> 30) == 0u);
                excl += (int)(st & 0x3FFFFFFFu);
                if ((st >> 30) == 2u) break;
                --j;
            }
            atomicExch(&g_state[b], (2u << 30) | (unsigned)(excl + total));
            sExcl = excl;
        }
    }
    __syncthreads();
    int rs = sExcl + incl - v;   // exclusive prefix
    if (gid < NN) { g_row_start[gid] = rs; g_cursor[gid] = rs; }
    if (gid == 0) g_row_start[NN] = EE;
}

// ---------------- CSR fill + scratch reset for next call ----------------
__global__ void k_fill(const int* __restrict__ ei) {
    int e = blockIdx.x * blockDim.x + threadIdx.x;
    if (e < EE) {
        int d = ei[EE + e];
        int pos = atomicAdd(&g_cursor[d], 1);
        g_csr[pos] = ei[e];
    }
    // g_cnt/g_state are dead after k_scan: reset them here for the next call
    if (e < NN) g_cnt[e] = 0;
    if (e < 256) g_state[e] = 0;
}

// ---------------- layer-1 mean aggregation (round-14 form: uint4 + cvt/FADD) ----------------
// Warp per node, half-warp per edge: lane=(sub,chunk), uint4 (8-half) loads.
// 2 edges per warp-iteration (x2 unroll = 4), fp32 accumulate, fp16 row out.
__global__ void k_agg1() {
    int warp = threadIdx.x >> 5, lane = threadIdx.x & 31;
    int node = blockIdx.x * 8 + warp;
    if (node >= NN) return;
    int beg = g_row_start[node], end = g_row_start[node + 1];
    int sub = lane >> 4, chunk = lane & 15;
    const uint4* xv = (const uint4*)g_x16;   // 16 uint4 per row
    float acc[8];
    #pragma unroll
    for (int i = 0; i < 8; ++i) acc[i] = 0.f;

    int e = beg;
    for (; e + 3 < end; e += 4) {
        int sA = g_csr[e + sub];
        int sB = g_csr[e + 2 + sub];
        uint4 dA = xv[(size_t)sA * 16 + chunk];
        uint4 dB = xv[(size_t)sB * 16 + chunk];
        float2 a0 = __half22float2(*(__half2*)&dA.x);
        float2 a1 = __half22float2(*(__half2*)&dA.y);
        float2 a2 = __half22float2(*(__half2*)&dA.z);
        float2 a3 = __half22float2(*(__half2*)&dA.w);
        float2 b0 = __half22float2(*(__half2*)&dB.x);
        float2 b1 = __half22float2(*(__half2*)&dB.y);
        float2 b2 = __half22float2(*(__half2*)&dB.z);
        float2 b3 = __half22float2(*(__half2*)&dB.w);
        acc[0] += a0.x + b0.x; acc[1] += a0.y + b0.y;
        acc[2] += a1.x + b1.x; acc[3] += a1.y + b1.y;
        acc[4] += a2.x + b2.x; acc[5] += a2.y + b2.y;
        acc[6] += a3.x + b3.x; acc[7] += a3.y + b3.y;
    }
    if (e + 1 < end) {       // one more pair
        int sA = g_csr[e + sub];
        uint4 dA = xv[(size_t)sA * 16 + chunk];
        float2 a0 = __half22float2(*(__half2*)&dA.x);
        float2 a1 = __half22float2(*(__half2*)&dA.y);
        float2 a2 = __half22float2(*(__half2*)&dA.z);
        float2 a3 = __half22float2(*(__half2*)&dA.w);
        acc[0] += a0.x; acc[1] += a0.y; acc[2] += a1.x; acc[3] += a1.y;
        acc[4] += a2.x; acc[5] += a2.y; acc[6] += a3.x; acc[7] += a3.y;
        e += 2;
    }
    if (e < end && sub == 0) {   // single-edge tail (sub 0 only)
        int sA = g_csr[e];
        uint4 dA = xv[(size_t)sA * 16 + chunk];
        float2 a0 = __half22float2(*(__half2*)&dA.x);
        float2 a1 = __half22float2(*(__half2*)&dA.y);
        float2 a2 = __half22float2(*(__half2*)&dA.z);
        float2 a3 = __half22float2(*(__half2*)&dA.w);
        acc[0] += a0.x; acc[1] += a0.y; acc[2] += a1.x; acc[3] += a1.y;
        acc[4] += a2.x; acc[5] += a2.y; acc[6] += a3.x; acc[7] += a3.y;
    }
    // combine the two half-warps
    #pragma unroll
    for (int i = 0; i < 8; ++i) acc[i] += __shfl_down_sync(FULL, acc[i], 16);
    if (sub == 0) {
        float inv = (end > beg) ? 1.0f / (float)(end - beg) : 0.f;
        uint4 o;
        *(__half2*)&o.x = __floats2half2_rn(acc[0] * inv, acc[1] * inv);
        *(__half2*)&o.y = __floats2half2_rn(acc[2] * inv, acc[3] * inv);
        *(__half2*)&o.z = __floats2half2_rn(acc[4] * inv, acc[5] * inv);
        *(__half2*)&o.w = __floats2half2_rn(acc[6] * inv, acc[7] * inv);
        ((uint4*)g_aggx16)[(size_t)node * 16 + chunk] = o;
    }
}

// ---------------- helpers ----------------
__device__ __forceinline__ uint32_t smem_u32(const void* p) {
    uint32_t a;
    asm("{ .reg .u64 t; cvta.to.shared.u64 t, %1; cvt.u32.u64 %0, t; }" : "=r"(a) : "l"(p));
    return a;
}
__device__ __forceinline__ void ldm_x4(uint32_t* r, uint32_t addr) {
    asm volatile("ldmatrix.sync.aligned.m8n8.x4.shared.b16 {%0,%1,%2,%3}, [%4];"
                 : "=r"(r[0]), "=r"(r[1]), "=r"(r[2]), "=r"(r[3]) : "r"(addr));
}
__device__ __forceinline__ void ldm_x2(uint32_t* r, uint32_t addr) {
    asm volatile("ldmatrix.sync.aligned.m8n8.x2.shared.b16 {%0,%1}, [%2];"
                 : "=r"(r[0]), "=r"(r[1]) : "r"(addr));
}
__device__ __forceinline__ void mma_f16(float* c, const uint32_t* a, const uint32_t* b) {
    asm volatile(
        "mma.sync.aligned.m16n8k16.row.col.f32.f16.f16.f32 "
        "{%0,%1,%2,%3}, {%4,%5,%6,%7}, {%8,%9}, {%0,%1,%2,%3};"
        : "+f"(c[0]), "+f"(c[1]), "+f"(c[2]), "+f"(c[3])
        : "r"(a[0]), "r"(a[1]), "r"(a[2]), "r"(a[3]), "r"(b[0]), "r"(b[1]));
}
__device__ __forceinline__ void cp16(uint32_t smem_addr, const void* gptr) {
    asm volatile("cp.async.cg.shared.global [%0], [%1], 16;"
                 :: "r"(smem_addr), "l"(gptr) : "memory");
}
__device__ __forceinline__ void cp16z(uint32_t smem_addr, const void* gptr, uint32_t sz) {
    asm volatile("cp.async.cg.shared.global [%0], [%1], 16, %2;"
                 :: "r"(smem_addr), "l"(gptr), "r"(sz) : "memory");
}
__device__ __forceinline__ void cp_commit() {
    asm volatile("cp.async.commit_group;" ::: "memory");
}
__device__ __forceinline__ void cp_wait0() {
    asm volatile("cp.async.wait_group 0;" ::: "memory");
}

// smem layout (bytes) — BM=128, double-buffered fp16 A/B tiles
#define SA    0            // 2 x [128][64] f16 swizzled   (2 x 16 KB)
#define SB    32768        // 2 x [256][64] f16 swizzled   (2 x 32 KB)
#define SM_W2 135168       // [8][256] f32 (8 KB) — placed after h-buffer region
#define SM_B1 143360       // [256] f32 (1 KB)
#define SM_TOT 144384
// h buffer [128][264] f32 = 135168 B reuses [0, 135168) after mainloop

// ---------------- mma.sync fp16 GEMM + fused layer-2 projection ----------------
// Per CTA: rows rowBase..rowBase+127, all 256 output cols. 16 warps (2x8),
// warp tile 64x32. D = A16 * W16 (fp32 accum). cp.async double buffering.
__global__ __launch_bounds__(512, 1) void k_mma(
    const float* __restrict__ b1,
    const float* __restrict__ w2l, const float* __restrict__ w2r)
{
    extern __shared__ char smem[];
    uint32_t sb = smem_u32(smem);
    int tid = threadIdx.x, wid = tid >> 5, lane = tid & 31;
    int rowBase = blockIdx.x * 128;
    int wr = wid & 1, wc = wid >> 1;           // warp grid: 2 rows x 8 cols

    int arow = tid >> 2, apart = tid & 3;      // A: 4 threads/row (128 rows), 2 x 16B each
    int grow = rowBase + arow;
    uint32_t asz = (grow < NN) ? 16u : 0u;     // zero-fill OOB rows

    int brow = tid >> 1, bhalf = tid & 1;      // B: 2 threads/row (256 rows), 4 x 16B each

    auto issueA = [&](int kc, int buf) {
        const __half* src = (kc < 2) ? (g_aggx16 + (size_t)grow * 128 + kc * 64)
                                     : (g_x16    + (size_t)grow * 128 + (kc - 2) * 64);
        uint32_t dst = sb + SA + buf * 16384 + arow * 128;
        #pragma unroll
        for (int q = 0; q < 2; ++q) {
            int c = apart * 2 + q;
            cp16z(dst + ((c ^ (arow & 7)) << 4), src + c * 8, asz);
        }
    };
    auto issueB = [&](int kc, int buf) {
        uint32_t dst = sb + SB + buf * 32768 + brow * 128;
        const __half* ph = g_w1h + brow * 256 + kc * 64 + bhalf * 32;
        #pragma unroll
        for (int q = 0; q < 4; ++q) {
            int c = bhalf * 4 + q;
            cp16(dst + ((c ^ (brow & 7)) << 4), ph + q * 8);
        }
    };

    // ---- prologue: kick off chunk 0, stage w2/b1 ----
    issueA(0, 0);
    issueB(0, 0);
    cp_commit();
    if (tid < 256) {
        int o = tid >> 5, k = (tid & 31) * 8;
        const float* wp = (o < 4) ? (w2l + o * 256 + k) : (w2r + (o - 4) * 256 + k);
        *(float4*)(smem + SM_W2 + (size_t)(o * 256 + k) * 4)     = ((const float4*)wp)[0];
        *(float4*)(smem + SM_W2 + (size_t)(o * 256 + k + 4) * 4) = ((const float4*)wp)[1];
        if (tid < 64) *(float4*)(smem + SM_B1 + tid * 16) = ((const float4*)b1)[tid];
    }

    float C[4][4][4];
    #pragma unroll
    for (int mt = 0; mt < 4; ++mt)
        #pragma unroll
        for (int nt = 0; nt < 4; ++nt)
            #pragma unroll
            for (int q = 0; q < 4; ++q) C[mt][nt][q] = 0.f;

    #pragma unroll
    for (int kc = 0; kc < 4; ++kc) {
        int buf = kc & 1;
        cp_wait0();
        __syncthreads();   // tiles[kc] visible to all; prior-buf reads done

        if (kc < 3) {      // overlap next chunk's loads with this chunk's MMAs
            issueA(kc + 1, buf ^ 1);
            issueB(kc + 1, buf ^ 1);
            cp_commit();
        }

        uint32_t baseA = sb + SA + buf * 16384;
        uint32_t baseB = sb + SB + buf * 32768;
        #pragma unroll
        for (int ks = 0; ks < 4; ++ks) {
            uint32_t Ah[4][4], Bh[4][2];
            int ar = lane & 15, ac = ks * 2 + (lane >> 4);
            #pragma unroll
            for (int mt = 0; mt < 4; ++mt) {
                int r = wr * 64 + mt * 16 + ar;
                ldm_x4(Ah[mt], baseA + r * 128 + ((ac ^ (r & 7)) << 4));
            }
            int br = lane & 7, bc = ks * 2 + ((lane >> 3) & 1);
            #pragma unroll
            for (int nt = 0; nt < 4; ++nt) {
                int r = wc * 32 + nt * 8 + br;
                ldm_x2(Bh[nt], baseB + r * 128 + ((bc ^ (r & 7)) << 4));
            }
            #pragma unroll
            for (int mt = 0; mt < 4; ++mt)
                #pragma unroll
                for (int nt = 0; nt < 4; ++nt)
                    mma_f16(C[mt][nt], Ah[mt], Bh[nt]);
        }
    }
    __syncthreads();   // all frag reads done; tile smem reusable as h buffer

    // ---- epilogue: bias + relu -> smem h[128][264] ----
    float* hs  = (float*)smem;
    const float* b1s = (const float*)(smem + SM_B1);
    const float* w2s = (const float*)(smem + SM_W2);
    {
        int rq = lane >> 2, cq = (lane & 3) * 2;
        #pragma unroll
        for (int mt = 0; mt < 4; ++mt)
            #pragma unroll
            for (int nt = 0; nt < 4; ++nt) {
                int col = wc * 32 + nt * 8 + cq;
                float bx = b1s[col], by = b1s[col + 1];
                int r0 = wr * 64 + mt * 16 + rq, r1 = r0 + 8;
                float v00 = C[mt][nt][0] + bx, v01 = C[mt][nt][1] + by;
                float v10 = C[mt][nt][2] + bx, v11 = C[mt][nt][3] + by;
                *(float2*)&hs[r0 * 264 + col] =
                    make_float2(v00 > 0.f ? v00 : 0.f, v01 > 0.f ? v01 : 0.f);
                *(float2*)&hs[r1 * 264 + col] =
                    make_float2(v10 > 0.f ? v10 : 0.f, v11 > 0.f ? v11 : 0.f);
            }
    }
    __syncthreads();

    // ---- layer-2 projection: warp per 8 rows (16 warps x 8 = 128 rows) ----
    #pragma unroll
    for (int rr = 0; rr < 8; ++rr) {
        int row = wid * 8 + rr;
        const float* hr = &hs[row * 264];
        float4 p0 = *(const float4*)&hr[lane * 8];
        float4 p1 = *(const float4*)&hr[lane * 8 + 4];
        float val = 0.f;
        #pragma unroll
        for (int o = 0; o < 8; ++o) {
            const float* wr2 = &w2s[o * 256 + lane * 8];
            float s = p0.x * wr2[0] + p0.y * wr2[1] + p0.z * wr2[2] + p0.w * wr2[3]
                    + p1.x * wr2[4] + p1.y * wr2[5] + p1.z * wr2[6] + p1.w * wr2[7];
            #pragma unroll
            for (int off = 16; off; off >>= 1) s += __shfl_xor_sync(FULL, s, off);
            if (lane == o) val = s;
        }
        int gr = rowBase + row;
        if (gr < NN) {
            if (lane < 4)      g_u[gr * 4 + lane]       = val;
            else if (lane < 8) g_v[gr * 4 + (lane - 4)] = val;
        }
    }
}

// ---------------- layer-2 aggregation + bias + residual + log_softmax ----------------
// Warp per node, lane per edge: float4 u-row loads, float4 accumulate,
// cross-lane shfl reduce, lane 0 does bias+residual+log_softmax.
__global__ void k_final(const float* __restrict__ b2, float* __restrict__ out) {
    int warp = threadIdx.x >> 5, lane = threadIdx.x & 31;
    int node = blockIdx.x * 8 + warp;
    if (node >= NN) return;
    int beg = g_row_start[node], end = g_row_start[node + 1];
    float4 acc = make_float4(0.f, 0.f, 0.f, 0.f);
    for (int e = beg + lane; e < end; e += 32) {
        int s = g_csr[e];
        float4 u = *(const float4*)&g_u[s * 4];
        acc.x += u.x; acc.y += u.y; acc.z += u.z; acc.w += u.w;
    }
    #pragma unroll
    for (int off = 16; off; off >>= 1) {
        acc.x += __shfl_down_sync(FULL, acc.x, off);
        acc.y += __shfl_down_sync(FULL, acc.y, off);
        acc.z += __shfl_down_sync(FULL, acc.z, off);
        acc.w += __shfl_down_sync(FULL, acc.w, off);
    }
    if (lane == 0) {
        float inv = (end > beg) ? 1.0f / (float)(end - beg) : 0.f;
        float4 v  = *(const float4*)&g_v[node * 4];
        float4 bb = *(const float4*)b2;
        float c0 = acc.x * inv + bb.x + v.x;
        float c1 = acc.y * inv + bb.y + v.y;
        float c2 = acc.z * inv + bb.z + v.z;
        float c3 = acc.w * inv + bb.w + v.w;
        float m = fmaxf(fmaxf(c0, c1), fmaxf(c2, c3));
        float ssum = expf(c0 - m) + expf(c1 - m) + expf(c2 - m) + expf(c3 - m);
        float lg = m + logf(ssum);
        *(float4*)&out[node * 4] = make_float4(c0 - lg, c1 - lg, c2 - lg, c3 - lg);
    }
}

// ---------------- eager module load + smem opt-in (static init, outside capture) ----------------
namespace {
struct HXModuleLoad {
    HXModuleLoad() {
        cudaFuncAttributes a;
        (void)cudaFuncGetAttributes(&a, (const void*)k_prep);
        (void)cudaFuncSetAttribute((const void*)k_mma,
                                   cudaFuncAttributeMaxDynamicSharedMemorySize, SM_TOT);
    }
};
HXModuleLoad hx_module_load_;
}

// ---------------- launch ----------------
extern "C" void kernel_launch(void* const* d_in, const int* in_sizes, int n_in,
                              void* d_out, int out_size) {
    const float* x   = (const float*)d_in[0];
    const int*   ei  = (const int*)d_in[1];   // int32 edge_index: [0..E)=src, [E..2E)=dst
    const float* w1l = (const float*)d_in[2];
    const float* w1r = (const float*)d_in[3];
    const float* b1  = (const float*)d_in[4];
    const float* w2l = (const float*)d_in[5];
    const float* w2r = (const float*)d_in[6];
    const float* b2  = (const float*)d_in[7];
    float* out = (float*)d_out;

    k_prep<<<512, 256>>>(w1l, w1r, x, ei);            // 1: W/x -> fp16 + histogram
    k_scan<<<NB_SCAN, 512>>>();                       // 2: single-pass lookback scan
    k_fill<<<(EE + 255) / 256, 256>>>(ei);            // 3: CSR fill + reset cnt/state
    k_agg1<<<(NN + 7) / 8, 256>>>();                  // 4: fp16 gather-mean (round-14 form)
    k_mma<<<(NN + 127) / 128, 512, SM_TOT>>>(b1, w2l, w2r);  // 5: BM=128
    k_final<<<(NN + 7) / 8, 256>>>(b2, out);          // 6: lane-per-edge float4 gather
}